// round 14
// baseline (speedup 1.0000x reference)
#include <cuda_runtime.h>
#include <math.h>

#define NQ 512
#define NK 1024
#define DIM 256
#define HEADS 8
#define HD 32
#define RPE 512
#define SCALE 0.17677669529663687f
#define FULLMASK 0xffffffffu

// ---------------- packed fp32x2 helpers ----------------------------------
__device__ __forceinline__ unsigned long long pk2(float lo, float hi) {
  unsigned long long r;
  asm("mov.b64 %0, {%1, %2};" : "=l"(r) : "f"(lo), "f"(hi));
  return r;
}
__device__ __forceinline__ void upk2(float& lo, float& hi, unsigned long long v) {
  asm("mov.b64 {%0, %1}, %2;" : "=f"(lo), "=f"(hi) : "l"(v));
}
__device__ __forceinline__ void fma2(unsigned long long& d, unsigned long long a,
                                     unsigned long long b) {
  asm("fma.rn.f32x2 %0, %1, %2, %0;" : "+l"(d) : "l"(a), "l"(b));
}

// ---------------- scratch (device globals; no allocation) ----------------
__device__ float g_q[NQ * DIM];
__device__ float g_kT[DIM * NK];  // K TRANSPOSED: [d][key]
__device__ float g_v[NK * DIM];
__device__ float g_tsort[RPE];
__device__ float g_F[HEADS * (RPE + 1)];
__device__ float g_G[HEADS * (RPE + 1)];
__device__ unsigned short g_sidx[NQ * NK];

// ---------------- CPB precompute: rank-count sort + shfl scans -----------
__global__ void __launch_bounds__(512) cpb_precompute(
    const float* __restrict__ W1v, const float* __restrict__ b1v,
    const float* __restrict__ W2v) {
  __shared__ float skey[RPE];
  __shared__ int sordinv[RPE];
  __shared__ float swtA[16][8];
  __shared__ float swtB[16][8];
  __shared__ float sF0[8], sG0[8];
  __shared__ float sTotW[8], sTotB[8];
  int t = threadIdx.x, lane = t & 31, warp = t >> 5;

  float w1 = W1v[t], bb = b1v[t];
  float key = (w1 != 0.f) ? (-bb / w1) : INFINITY;
  skey[t] = key;
  __syncthreads();

  // rank = #{j : key_j < key_t or (key_j == key_t and j < t)}
  int rank = 0;
#pragma unroll 4
  for (int j4 = 0; j4 < RPE / 4; j4++) {
    float4 kj = *(const float4*)&skey[j4 * 4];
    int jb = j4 * 4;
    rank += (kj.x < key || (kj.x == key && (jb + 0) < t)) ? 1 : 0;
    rank += (kj.y < key || (kj.y == key && (jb + 1) < t)) ? 1 : 0;
    rank += (kj.z < key || (kj.z == key && (jb + 2) < t)) ? 1 : 0;
    rank += (kj.w < key || (kj.w == key && (jb + 3) < t)) ? 1 : 0;
  }
  g_tsort[rank] = key;
  sordinv[rank] = t;
  __syncthreads();

  int r = sordinv[t];
  float w1r = W1v[r], b1r = b1v[r];
  bool isPos = (w1r > 0.f), isNeg = (w1r < 0.f);
  bool isZero = (!isPos && !isNeg);
  float sgn = isPos ? 1.f : (isNeg ? -1.f : 0.f);

  float ocw[8], ocb[8], cw[8], cb[8], f0[8], g0[8];
#pragma unroll
  for (int h = 0; h < 8; h++) {
    float w2 = W2v[r * HEADS + h];
    ocw[h] = sgn * w1r * w2;
    ocb[h] = sgn * b1r * w2;
    cw[h] = ocw[h];
    cb[h] = ocb[h];
    f0[h] = isNeg ? (w1r * w2) : 0.f;
    g0[h] = isNeg ? (b1r * w2) : ((isZero && b1r > 0.f) ? (b1r * w2) : 0.f);
  }

#pragma unroll
  for (int o = 16; o; o >>= 1)
#pragma unroll
    for (int h = 0; h < 8; h++) {
      f0[h] += __shfl_xor_sync(FULLMASK, f0[h], o);
      g0[h] += __shfl_xor_sync(FULLMASK, g0[h], o);
    }
  if (lane == 0)
#pragma unroll
    for (int h = 0; h < 8; h++) {
      swtA[warp][h] = f0[h];
      swtB[warp][h] = g0[h];
    }
  __syncthreads();
  if (t < 8) {
    float sa = 0.f, sb = 0.f;
    for (int ww = 0; ww < 16; ww++) {
      sa += swtA[ww][t];
      sb += swtB[ww][t];
    }
    sF0[t] = sa;
    sG0[t] = sb;
  }
  __syncthreads();

#pragma unroll
  for (int o = 1; o < 32; o <<= 1) {
#pragma unroll
    for (int h = 0; h < 8; h++) {
      float ta = __shfl_up_sync(FULLMASK, cw[h], o);
      float tb = __shfl_up_sync(FULLMASK, cb[h], o);
      if (lane >= o) {
        cw[h] += ta;
        cb[h] += tb;
      }
    }
  }
  if (lane == 31)
#pragma unroll
    for (int h = 0; h < 8; h++) {
      swtA[warp][h] = cw[h];
      swtB[warp][h] = cb[h];
    }
  __syncthreads();

  if (warp == 0) {
    float va[8], vb[8], owa[8], owb[8];
#pragma unroll
    for (int h = 0; h < 8; h++) {
      owa[h] = (lane < 16) ? swtA[lane][h] : 0.f;
      owb[h] = (lane < 16) ? swtB[lane][h] : 0.f;
      va[h] = owa[h];
      vb[h] = owb[h];
    }
#pragma unroll
    for (int o = 1; o < 16; o <<= 1)
#pragma unroll
      for (int h = 0; h < 8; h++) {
        float ta = __shfl_up_sync(FULLMASK, va[h], o);
        float tb = __shfl_up_sync(FULLMASK, vb[h], o);
        if (lane >= o) {
          va[h] += ta;
          vb[h] += tb;
        }
      }
    if (lane < 16) {
#pragma unroll
      for (int h = 0; h < 8; h++) {
        swtA[lane][h] = va[h] - owa[h];
        swtB[lane][h] = vb[h] - owb[h];
        if (lane == 15) {
          sTotW[h] = va[h];
          sTotB[h] = vb[h];
        }
      }
    }
  }
  __syncthreads();

#pragma unroll
  for (int h = 0; h < 8; h++) {
    float excl = (cw[h] - ocw[h]) + swtA[warp][h];
    float exclb = (cb[h] - ocb[h]) + swtB[warp][h];
    g_F[h * (RPE + 1) + t] = sF0[h] + excl;
    g_G[h * (RPE + 1) + t] = sG0[h] + exclb;
  }
  if (t == 0)
#pragma unroll
    for (int h = 0; h < 8; h++) {
      g_F[h * (RPE + 1) + RPE] = sF0[h] + sTotW[h];
      g_G[h * (RPE + 1) + RPE] = sG0[h] + sTotB[h];
    }
}

// ---------------- mid: QKV GEMMs + cpb_index + out init, one launch ------
// blocks 0..159: two 128-thread GEMM tile groups each (320 tiles total)
//   tile id: Q 0..63, K 64..191 (transposed scatter store), V 192..319
// blocks 160..671: cpb_index rows + d_out init (reads g_tsort from launch 1)
__global__ void __launch_bounds__(256) mid(
    const float* __restrict__ query, const float* __restrict__ kin,
    const float* __restrict__ vin,
    const float* __restrict__ Wq, const float* __restrict__ bq,
    const float* __restrict__ Wk, const float* __restrict__ bk,
    const float* __restrict__ Wv, const float* __restrict__ bv,
    const float* __restrict__ am, const float* __restrict__ bp,
    float* __restrict__ outp) {
  int t = threadIdx.x;
  if (blockIdx.x < 160) {
    __shared__ float As[2][16][36];
    __shared__ float Bs[2][16][64];
    int g = t >> 7, lt = t & 127;
    int id = blockIdx.x * 2 + g;  // 0..319, all active
    int sel, tloc;
    if (id < 64) { sel = 0; tloc = id; }
    else if (id < 192) { sel = 1; tloc = id - 64; }
    else { sel = 2; tloc = id - 192; }
    const float* A = (sel == 0) ? query : (sel == 1) ? kin : vin;
    const float* W = (sel == 0) ? Wq : (sel == 1) ? Wk : Wv;
    const float* bias = (sel == 0) ? bq : (sel == 1) ? bk : bv;
    int bm = (tloc >> 2) * 32;
    int bn = (tloc & 3) * 64;

    int tx = lt % 16, ty = lt / 16;
    float acc[4][4] = {};

    for (int k0 = 0; k0 < 256; k0 += 16) {
      {  // A tile 32x16, transposed into As[k][row]
        int r = lt >> 2, c4 = lt & 3;
        float4 av = *(const float4*)&A[(bm + r) * 256 + k0 + c4 * 4];
        As[g][c4 * 4 + 0][r] = av.x;
        As[g][c4 * 4 + 1][r] = av.y;
        As[g][c4 * 4 + 2][r] = av.z;
        As[g][c4 * 4 + 3][r] = av.w;
      }
#pragma unroll
      for (int u = 0; u < 2; u++) {  // W tile 16x64
        int idx = lt * 2 + u;
        int rr = idx >> 4, cc = idx & 15;
        *(float4*)&Bs[g][rr][cc * 4] =
            *(const float4*)&W[(k0 + rr) * 256 + bn + cc * 4];
      }
      __syncthreads();
#pragma unroll
      for (int k = 0; k < 16; k++) {
        float a[4], b[4];
#pragma unroll
        for (int i = 0; i < 4; i++) a[i] = As[g][k][ty * 4 + i];
#pragma unroll
        for (int j = 0; j < 4; j++) b[j] = Bs[g][k][tx * 4 + j];
#pragma unroll
        for (int i = 0; i < 4; i++)
#pragma unroll
          for (int j = 0; j < 4; j++) acc[i][j] = fmaf(a[i], b[j], acc[i][j]);
      }
      __syncthreads();
    }
    if (sel == 0) {
#pragma unroll
      for (int i = 0; i < 4; i++) {
        int row = bm + ty * 4 + i;
#pragma unroll
        for (int j = 0; j < 4; j++) {
          int col = bn + tx * 4 + j;
          g_q[row * 256 + col] = acc[i][j] + bias[col];
        }
      }
    } else if (sel == 2) {
#pragma unroll
      for (int i = 0; i < 4; i++) {
        int row = bm + ty * 4 + i;
#pragma unroll
        for (int j = 0; j < 4; j++) {
          int col = bn + tx * 4 + j;
          g_v[row * 256 + col] = acc[i][j] + bias[col];
        }
      }
    } else {  // K: transposed scatter store g_kT[col][row] (proven path)
#pragma unroll
      for (int i = 0; i < 4; i++) {
        int row = bm + ty * 4 + i;
#pragma unroll
        for (int j = 0; j < 4; j++) {
          int col = bn + tx * 4 + j;
          g_kT[col * NK + row] = acc[i][j] + bias[col];
        }
      }
    }
    return;
  }

  // ---------------- cpb_index part (blocks 160..671) ----------------
  __shared__ float st[RPE];
  int b = blockIdx.x - 160;  // 0..511
  for (int i = t; i < RPE; i += 256) st[i] = g_tsort[i];
  outp[b * 256 + t] = bp[t];  // init d_out with bias
  __syncthreads();
  int base = (b * 256 + t) * 4;
  float4 a4 = *(const float4*)&am[base];
  float av[4] = {a4.x, a4.y, a4.z, a4.w};
  unsigned short res[4];
#pragma unroll
  for (int u = 0; u < 4; u++) {
    int pos = 0;
#pragma unroll
    for (int sgm = 256; sgm >= 1; sgm >>= 1)
      if (st[pos + sgm - 1] < av[u]) pos += sgm;
    res[u] = (unsigned short)pos;
  }
  *(ushort4*)&g_sidx[base] = make_ushort4(res[0], res[1], res[2], res[3]);
}

// ---------------- fused attention + output projection --------------------
struct AttnSmem {
  float sQ[8][32];  // @0: scaled Q, later reused as x-slice for projection
  union {
    float sP[NK][8];       // 32KB: normalized probs (single pass)
    float sOut[8][8][32];  // 8KB epilogue
  } u;                     // @1024
  float sRed[8][8];        // @33792 (16B aligned)
  float sF[RPE + 4];
  float sG[RPE + 4];
};  // ~37.3KB static

__global__ void __launch_bounds__(256, 4) attention(
    const float* __restrict__ pad, const float* __restrict__ am,
    const float* __restrict__ Wp, float* __restrict__ outp) {
  __shared__ AttnSmem S;
  const int h = blockIdx.y;
  const int q0 = blockIdx.x * 8;
  const int t = threadIdx.x;
  const int lane = t & 31, w = t >> 5;
  const int kbase = 4 * t;

  S.sQ[w][lane] = g_q[(q0 + w) * DIM + h * HD + lane] * SCALE;
  for (int i = t; i <= RPE; i += 256) {
    S.sF[i] = g_F[h * (RPE + 1) + i];
    S.sG[i] = g_G[h * (RPE + 1) + i];
  }
  __syncthreads();

  // ---- QK: acc[kg][qi], K via transposed coalesced LDG ----
  float acc[4][8];
#pragma unroll
  for (int kg = 0; kg < 4; kg++)
#pragma unroll
    for (int qi = 0; qi < 8; qi++) acc[kg][qi] = 0.f;

#pragma unroll
  for (int c = 0; c < 8; c++) {
    const float* kp = &g_kT[(h * HD + c * 4) * NK + kbase];
    float4 kq0 = *(const float4*)&kp[0 * NK];
    float4 kq1 = *(const float4*)&kp[1 * NK];
    float4 kq2 = *(const float4*)&kp[2 * NK];
    float4 kq3 = *(const float4*)&kp[3 * NK];
#pragma unroll
    for (int qi = 0; qi < 8; qi++) {
      float4 qv = *(const float4*)&S.sQ[qi][c * 4];
      acc[0][qi] = fmaf(qv.x, kq0.x, acc[0][qi]);
      acc[0][qi] = fmaf(qv.y, kq1.x, acc[0][qi]);
      acc[0][qi] = fmaf(qv.z, kq2.x, acc[0][qi]);
      acc[0][qi] = fmaf(qv.w, kq3.x, acc[0][qi]);
      acc[1][qi] = fmaf(qv.x, kq0.y, acc[1][qi]);
      acc[1][qi] = fmaf(qv.y, kq1.y, acc[1][qi]);
      acc[1][qi] = fmaf(qv.z, kq2.y, acc[1][qi]);
      acc[1][qi] = fmaf(qv.w, kq3.y, acc[1][qi]);
      acc[2][qi] = fmaf(qv.x, kq0.z, acc[2][qi]);
      acc[2][qi] = fmaf(qv.y, kq1.z, acc[2][qi]);
      acc[2][qi] = fmaf(qv.z, kq2.z, acc[2][qi]);
      acc[2][qi] = fmaf(qv.w, kq3.z, acc[2][qi]);
      acc[3][qi] = fmaf(qv.x, kq0.w, acc[3][qi]);
      acc[3][qi] = fmaf(qv.y, kq1.w, acc[3][qi]);
      acc[3][qi] = fmaf(qv.z, kq2.w, acc[3][qi]);
      acc[3][qi] = fmaf(qv.w, kq3.w, acc[3][qi]);
    }
  }

  // ---- CPB bias + padding ----
  {
    float4 p4 = *(const float4*)&pad[kbase];
    float pv[4] = {100.f * p4.x, 100.f * p4.y, 100.f * p4.z, 100.f * p4.w};
#pragma unroll
    for (int qi = 0; qi < 8; qi++) {
      float4 a4 = *(const float4*)&am[(q0 + qi) * NK + kbase];
      ushort4 x4 = *(const ushort4*)&g_sidx[(q0 + qi) * NK + kbase];
      acc[0][qi] += fmaf(a4.x, S.sF[x4.x], S.sG[x4.x]) - pv[0];
      acc[1][qi] += fmaf(a4.y, S.sF[x4.y], S.sG[x4.y]) - pv[1];
      acc[2][qi] += fmaf(a4.z, S.sF[x4.z], S.sG[x4.z]) - pv[2];
      acc[3][qi] += fmaf(a4.w, S.sF[x4.w], S.sG[x4.w]) - pv[3];
    }
  }

  // ---- block max per query ----
  float m[8];
#pragma unroll
  for (int qi = 0; qi < 8; qi++)
    m[qi] = fmaxf(fmaxf(acc[0][qi], acc[1][qi]), fmaxf(acc[2][qi], acc[3][qi]));
#pragma unroll
  for (int o = 16; o; o >>= 1)
#pragma unroll
    for (int qi = 0; qi < 8; qi++)
      m[qi] = fmaxf(m[qi], __shfl_xor_sync(FULLMASK, m[qi], o));
  if (lane == 0)
#pragma unroll
    for (int qi = 0; qi < 8; qi++) S.sRed[qi][w] = m[qi];
  __syncthreads();
#pragma unroll
  for (int qi = 0; qi < 8; qi++) {
    float4 r0 = *(const float4*)&S.sRed[qi][0];
    float4 r1 = *(const float4*)&S.sRed[qi][4];
    m[qi] = fmaxf(fmaxf(fmaxf(r0.x, r0.y), fmaxf(r0.z, r0.w)),
                  fmaxf(fmaxf(r1.x, r1.y), fmaxf(r1.z, r1.w)));
  }

  // ---- exp + sum ----
  float s[8];
#pragma unroll
  for (int qi = 0; qi < 8; qi++) {
    float e0 = __expf(acc[0][qi] - m[qi]);
    float e1 = __expf(acc[1][qi] - m[qi]);
    float e2 = __expf(acc[2][qi] - m[qi]);
    float e3 = __expf(acc[3][qi] - m[qi]);
    acc[0][qi] = e0;
    acc[1][qi] = e1;
    acc[2][qi] = e2;
    acc[3][qi] = e3;
    s[qi] = (e0 + e1) + (e2 + e3);
  }
#pragma unroll
  for (int o = 16; o; o >>= 1)
#pragma unroll
    for (int qi = 0; qi < 8; qi++)
      s[qi] += __shfl_xor_sync(FULLMASK, s[qi], o);
  __syncthreads();  // all sRed max reads done
  if (lane == 0)
#pragma unroll
    for (int qi = 0; qi < 8; qi++) S.sRed[qi][w] = s[qi];
  __syncthreads();
  float inv[8];
#pragma unroll
  for (int qi = 0; qi < 8; qi++) {
    float4 r0 = *(const float4*)&S.sRed[qi][0];
    float4 r1 = *(const float4*)&S.sRed[qi][4];
    inv[qi] = 1.f / ((r0.x + r0.y) + (r0.z + r0.w) + (r1.x + r1.y) + (r1.z + r1.w));
  }

  // ---- store NORMALIZED probs (all 8 queries, single pass) ----
#pragma unroll
  for (int kg = 0; kg < 4; kg++) {
    *(float4*)&S.u.sP[kbase + kg][0] =
        make_float4(acc[kg][0] * inv[0], acc[kg][1] * inv[1],
                    acc[kg][2] * inv[2], acc[kg][3] * inv[3]);
    *(float4*)&S.u.sP[kbase + kg][4] =
        make_float4(acc[kg][4] * inv[4], acc[kg][5] * inv[5],
                    acc[kg][6] * inv[6], acc[kg][7] * inv[7]);
  }
  __syncthreads();

  // ---- AV single pass: warp owns keys [w*128, w*128+128); f32x2 ----
  unsigned long long out2[4] = {0ull, 0ull, 0ull, 0ull};
  const float* vb = &g_v[(w * 128) * DIM + h * HD + lane];
#pragma unroll 8
  for (int jj = 0; jj < 128; jj++) {
    float vv = __ldg(&vb[jj * DIM]);
    unsigned long long vvp = pk2(vv, vv);
    ulonglong2 p01 = *(const ulonglong2*)&S.u.sP[w * 128 + jj][0];
    ulonglong2 p23 = *(const ulonglong2*)&S.u.sP[w * 128 + jj][4];
    fma2(out2[0], p01.x, vvp);
    fma2(out2[1], p01.y, vvp);
    fma2(out2[2], p23.x, vvp);
    fma2(out2[3], p23.y, vvp);
  }
  __syncthreads();  // all sP reads done before sOut alias write

  // ---- cross-warp x reduction into sQ (x-slice [8q][32d]) ----
  float out[8];
#pragma unroll
  for (int p = 0; p < 4; p++) upk2(out[2 * p], out[2 * p + 1], out2[p]);
#pragma unroll
  for (int qi = 0; qi < 8; qi++) S.u.sOut[w][qi][lane] = out[qi];
  __syncthreads();
  {
    float accf = 0.f;
#pragma unroll
    for (int ww = 0; ww < 8; ww++) accf += S.u.sOut[ww][w][lane];
    S.sQ[w][lane] = accf;  // x[q0+w][h*32+lane]
  }
  __syncthreads();

  // ---- fused output projection: (8x32 x-slice) @ Wp[h*32: , :] ----
  float acc8[8] = {};
  const float* wp = &Wp[(h * HD) * DIM + t];
#pragma unroll
  for (int d4 = 0; d4 < 8; d4++) {
    float wv0 = __ldg(&wp[(d4 * 4 + 0) * DIM]);
    float wv1 = __ldg(&wp[(d4 * 4 + 1) * DIM]);
    float wv2 = __ldg(&wp[(d4 * 4 + 2) * DIM]);
    float wv3 = __ldg(&wp[(d4 * 4 + 3) * DIM]);
#pragma unroll
    for (int qi = 0; qi < 8; qi++) {
      float4 xv = *(const float4*)&S.sQ[qi][d4 * 4];
      acc8[qi] = fmaf(xv.x, wv0, acc8[qi]);
      acc8[qi] = fmaf(xv.y, wv1, acc8[qi]);
      acc8[qi] = fmaf(xv.z, wv2, acc8[qi]);
      acc8[qi] = fmaf(xv.w, wv3, acc8[qi]);
    }
  }
#pragma unroll
  for (int qi = 0; qi < 8; qi++)
    atomicAdd(&outp[(q0 + qi) * DIM + t], acc8[qi]);
}

// ---------------- launch ------------------------------------------------
extern "C" void kernel_launch(void* const* d_in, const int* in_sizes, int n_in,
                              void* d_out, int out_size) {
  const float* query = (const float*)d_in[0];
  const float* kin   = (const float*)d_in[1];
  const float* vin   = (const float*)d_in[2];
  const float* pad   = (const float*)d_in[3];
  const float* am    = (const float*)d_in[4];
  const float* Wq    = (const float*)d_in[5];
  const float* bq    = (const float*)d_in[6];
  const float* Wk    = (const float*)d_in[7];
  const float* bk    = (const float*)d_in[8];
  const float* Wv    = (const float*)d_in[9];
  const float* bv    = (const float*)d_in[10];
  const float* Wp    = (const float*)d_in[11];
  const float* bp    = (const float*)d_in[12];
  const float* W1    = (const float*)d_in[13];
  const float* b1    = (const float*)d_in[14];
  const float* W2    = (const float*)d_in[15];
  float* out = (float*)d_out;

  cpb_precompute<<<1, RPE>>>(W1, b1, W2);
  mid<<<672, 256>>>(query, kin, vin, Wq, bq, Wk, bk, Wv, bv, am, bp, out);
  attention<<<dim3(NQ / 8, HEADS), 256>>>(pad, am, Wp, out);
}

// round 15
// speedup vs baseline: 1.1100x; 1.1100x over previous
#include <cuda_runtime.h>
#include <math.h>

#define NQ 512
#define NK 1024
#define DIM 256
#define HEADS 8
#define HD 32
#define RPE 512
#define SCALE 0.17677669529663687f
#define FULLMASK 0xffffffffu

// ---------------- packed fp32x2 helpers ----------------------------------
__device__ __forceinline__ unsigned long long pk2(float lo, float hi) {
  unsigned long long r;
  asm("mov.b64 %0, {%1, %2};" : "=l"(r) : "f"(lo), "f"(hi));
  return r;
}
__device__ __forceinline__ void upk2(float& lo, float& hi, unsigned long long v) {
  asm("mov.b64 {%0, %1}, %2;" : "=f"(lo), "=f"(hi) : "l"(v));
}
__device__ __forceinline__ void fma2(unsigned long long& d, unsigned long long a,
                                     unsigned long long b) {
  asm("fma.rn.f32x2 %0, %1, %2, %0;" : "+l"(d) : "l"(a), "l"(b));
}

// ---------------- scratch (device globals; no allocation) ----------------
__device__ float g_q[NQ * DIM];
__device__ float g_kT[DIM * NK];  // K TRANSPOSED: [d][key]
__device__ float g_v[NK * DIM];
__device__ float g_tsort[RPE];
__device__ int g_sord[RPE];
__device__ float g_F[HEADS * (RPE + 1)];
__device__ float g_G[HEADS * (RPE + 1)];
__device__ unsigned short g_sidx[NQ * NK];

// ---------------- cpb_sort: keys + rank-count sort only ------------------
__global__ void __launch_bounds__(512) cpb_sort(const float* __restrict__ W1v,
                                                const float* __restrict__ b1v) {
  __shared__ float skey[RPE];
  int t = threadIdx.x;
  float w1 = W1v[t], bb = b1v[t];
  float key = (w1 != 0.f) ? (-bb / w1) : INFINITY;
  skey[t] = key;
  __syncthreads();
  int rank = 0;
#pragma unroll 4
  for (int j4 = 0; j4 < RPE / 4; j4++) {
    float4 kj = *(const float4*)&skey[j4 * 4];
    int jb = j4 * 4;
    rank += (kj.x < key || (kj.x == key && (jb + 0) < t)) ? 1 : 0;
    rank += (kj.y < key || (kj.y == key && (jb + 1) < t)) ? 1 : 0;
    rank += (kj.z < key || (kj.z == key && (jb + 2) < t)) ? 1 : 0;
    rank += (kj.w < key || (kj.w == key && (jb + 3) < t)) ? 1 : 0;
  }
  g_tsort[rank] = key;
  g_sord[rank] = t;
}

// ---------------- mid: QKV GEMMs + cpb_index + CPB tables, one launch ----
// blocks 0..159   : two 128-thread GEMM tile groups (320 tiles)
// blocks 160..671 : cpb_index rows + d_out init (uses g_tsort)
// blocks 672..679 : F/G table build for head (blockIdx.x-672) (uses g_sord)
__global__ void __launch_bounds__(256) mid(
    const float* __restrict__ query, const float* __restrict__ kin,
    const float* __restrict__ vin,
    const float* __restrict__ Wq, const float* __restrict__ bq,
    const float* __restrict__ Wk, const float* __restrict__ bk,
    const float* __restrict__ Wv, const float* __restrict__ bv,
    const float* __restrict__ am, const float* __restrict__ bp,
    const float* __restrict__ W1v, const float* __restrict__ b1v,
    const float* __restrict__ W2v, float* __restrict__ outp) {
  int t = threadIdx.x;
  __shared__ float As[2][16][36];
  __shared__ float Bs[2][16][64];
  __shared__ float st[RPE];
  __shared__ float swt[8][4];
  __shared__ float sRed2[2][8];

  if (blockIdx.x < 160) {
    int g = t >> 7, lt = t & 127;
    int id = blockIdx.x * 2 + g;  // 0..319, all active
    int sel, tloc;
    if (id < 64) { sel = 0; tloc = id; }
    else if (id < 192) { sel = 1; tloc = id - 64; }
    else { sel = 2; tloc = id - 192; }
    const float* A = (sel == 0) ? query : (sel == 1) ? kin : vin;
    const float* W = (sel == 0) ? Wq : (sel == 1) ? Wk : Wv;
    const float* bias = (sel == 0) ? bq : (sel == 1) ? bk : bv;
    int bm = (tloc >> 2) * 32;
    int bn = (tloc & 3) * 64;

    int tx = lt % 16, ty = lt / 16;
    float acc[4][4] = {};

    for (int k0 = 0; k0 < 256; k0 += 16) {
      {
        int r = lt >> 2, c4 = lt & 3;
        float4 av = *(const float4*)&A[(bm + r) * 256 + k0 + c4 * 4];
        As[g][c4 * 4 + 0][r] = av.x;
        As[g][c4 * 4 + 1][r] = av.y;
        As[g][c4 * 4 + 2][r] = av.z;
        As[g][c4 * 4 + 3][r] = av.w;
      }
#pragma unroll
      for (int u = 0; u < 2; u++) {
        int idx = lt * 2 + u;
        int rr = idx >> 4, cc = idx & 15;
        *(float4*)&Bs[g][rr][cc * 4] =
            *(const float4*)&W[(k0 + rr) * 256 + bn + cc * 4];
      }
      __syncthreads();
#pragma unroll
      for (int k = 0; k < 16; k++) {
        float a[4], b[4];
#pragma unroll
        for (int i = 0; i < 4; i++) a[i] = As[g][k][ty * 4 + i];
#pragma unroll
        for (int j = 0; j < 4; j++) b[j] = Bs[g][k][tx * 4 + j];
#pragma unroll
        for (int i = 0; i < 4; i++)
#pragma unroll
          for (int j = 0; j < 4; j++) acc[i][j] = fmaf(a[i], b[j], acc[i][j]);
      }
      __syncthreads();
    }
    if (sel == 0) {
#pragma unroll
      for (int i = 0; i < 4; i++) {
        int row = bm + ty * 4 + i;
#pragma unroll
        for (int j = 0; j < 4; j++) {
          int col = bn + tx * 4 + j;
          g_q[row * 256 + col] = acc[i][j] + bias[col];
        }
      }
    } else if (sel == 2) {
#pragma unroll
      for (int i = 0; i < 4; i++) {
        int row = bm + ty * 4 + i;
#pragma unroll
        for (int j = 0; j < 4; j++) {
          int col = bn + tx * 4 + j;
          g_v[row * 256 + col] = acc[i][j] + bias[col];
        }
      }
    } else {  // K: transposed scatter store (proven path)
#pragma unroll
      for (int i = 0; i < 4; i++) {
        int row = bm + ty * 4 + i;
#pragma unroll
        for (int j = 0; j < 4; j++) {
          int col = bn + tx * 4 + j;
          g_kT[col * NK + row] = acc[i][j] + bias[col];
        }
      }
    }
    return;
  }

  if (blockIdx.x < 672) {
    // ---------------- cpb_index part ----------------
    int b = blockIdx.x - 160;  // 0..511
    for (int i = t; i < RPE; i += 256) st[i] = g_tsort[i];
    outp[b * 256 + t] = bp[t];  // init d_out with bias
    __syncthreads();
    int base = (b * 256 + t) * 4;
    float4 a4 = *(const float4*)&am[base];
    float av[4] = {a4.x, a4.y, a4.z, a4.w};
    unsigned short res[4];
#pragma unroll
    for (int u = 0; u < 4; u++) {
      int pos = 0;
#pragma unroll
      for (int sgm = 256; sgm >= 1; sgm >>= 1)
        if (st[pos + sgm - 1] < av[u]) pos += sgm;
      res[u] = (unsigned short)pos;
    }
    *(ushort4*)&g_sidx[base] = make_ushort4(res[0], res[1], res[2], res[3]);
    return;
  }

  // ---------------- CPB table build for one head ----------------
  {
    int h = blockIdx.x - 672;
    int lane = t & 31, warp = t >> 5;  // 8 warps

    // slots u0=t (first half), u1=t+256 (second half)
    int r0 = g_sord[t], r1 = g_sord[t + 256];

    float w1a = W1v[r0], b1a = b1v[r0], w2a = W2v[r0 * HEADS + h];
    bool negA = (w1a < 0.f), posA = (w1a > 0.f), zeroA = (!negA && !posA);
    float sgnA = posA ? 1.f : (negA ? -1.f : 0.f);
    float cwA = sgnA * w1a * w2a, cbA = sgnA * b1a * w2a;
    float f0A = negA ? (w1a * w2a) : 0.f;
    float g0A = negA ? (b1a * w2a) : ((zeroA && b1a > 0.f) ? (b1a * w2a) : 0.f);

    float w1b = W1v[r1], b1b = b1v[r1], w2b = W2v[r1 * HEADS + h];
    bool negB = (w1b < 0.f), posB = (w1b > 0.f), zeroB = (!negB && !posB);
    float sgnB = posB ? 1.f : (negB ? -1.f : 0.f);
    float cwB = sgnB * w1b * w2b, cbB = sgnB * b1b * w2b;
    float f0B = negB ? (w1b * w2b) : 0.f;
    float g0B = negB ? (b1b * w2b) : ((zeroB && b1b > 0.f) ? (b1b * w2b) : 0.f);

    // F0/G0 block reduction
    float fr = f0A + f0B, gr = g0A + g0B;
#pragma unroll
    for (int o = 16; o; o >>= 1) {
      fr += __shfl_xor_sync(FULLMASK, fr, o);
      gr += __shfl_xor_sync(FULLMASK, gr, o);
    }
    if (lane == 0) {
      sRed2[0][warp] = fr;
      sRed2[1][warp] = gr;
    }
    __syncthreads();
    float F0 = 0.f, G0 = 0.f;
#pragma unroll
    for (int ww = 0; ww < 8; ww++) {
      F0 += sRed2[0][ww];
      G0 += sRed2[1][ww];
    }
    __syncthreads();

    // inclusive warp scans of 4 quantities
    float sc[4] = {cwA, cbA, cwB, cbB};
    float orig[4] = {cwA, cbA, cwB, cbB};
#pragma unroll
    for (int o = 1; o < 32; o <<= 1) {
#pragma unroll
      for (int q = 0; q < 4; q++) {
        float v = __shfl_up_sync(FULLMASK, sc[q], o);
        if (lane >= o) sc[q] += v;
      }
    }
    if (lane == 31)
#pragma unroll
      for (int q = 0; q < 4; q++) swt[warp][q] = sc[q];
    __syncthreads();
    float woff[4] = {0.f, 0.f, 0.f, 0.f};
    float tot[4] = {0.f, 0.f, 0.f, 0.f};
#pragma unroll
    for (int ww = 0; ww < 8; ww++)
#pragma unroll
      for (int q = 0; q < 4; q++) {
        float v = swt[ww][q];
        if (ww < warp) woff[q] += v;
        tot[q] += v;
      }
    float excl[4];
#pragma unroll
    for (int q = 0; q < 4; q++) excl[q] = sc[q] + woff[q] - orig[q];

    // write F/G
    float* Fh = &g_F[h * (RPE + 1)];
    float* Gh = &g_G[h * (RPE + 1)];
    Fh[t] = F0 + excl[0];
    Gh[t] = G0 + excl[1];
    Fh[t + 256] = F0 + tot[0] + excl[2];
    Gh[t + 256] = G0 + tot[1] + excl[3];
    if (t == 0) {
      Fh[RPE] = F0 + tot[0] + tot[2];
      Gh[RPE] = G0 + tot[1] + tot[3];
    }
  }
}

// ---------------- fused attention + output projection --------------------
struct AttnSmem {
  float sQ[8][32];  // @0: scaled Q, later reused as x-slice for projection
  union {
    float sP[NK][8];       // 32KB: normalized probs (single pass)
    float sOut[8][8][32];  // 8KB epilogue
  } u;                     // @1024
  float sRed[8][8];        // @33792 (16B aligned)
  float2 sFG[RPE + 4];     // interleaved F/G tables
};  // ~37.3KB static

__global__ void __launch_bounds__(256, 4) attention(
    const float* __restrict__ pad, const float* __restrict__ am,
    const float* __restrict__ Wp, float* __restrict__ outp) {
  __shared__ AttnSmem S;
  const int h = blockIdx.y;
  const int q0 = blockIdx.x * 8;
  const int t = threadIdx.x;
  const int lane = t & 31, w = t >> 5;
  const int kbase = 4 * t;

  S.sQ[w][lane] = g_q[(q0 + w) * DIM + h * HD + lane] * SCALE;
  for (int i = t; i <= RPE; i += 256)
    S.sFG[i] = make_float2(g_F[h * (RPE + 1) + i], g_G[h * (RPE + 1) + i]);
  __syncthreads();

  // ---- QK: acc[kg][qi], K via transposed coalesced LDG ----
  float acc[4][8];
#pragma unroll
  for (int kg = 0; kg < 4; kg++)
#pragma unroll
    for (int qi = 0; qi < 8; qi++) acc[kg][qi] = 0.f;

#pragma unroll
  for (int c = 0; c < 8; c++) {
    const float* kp = &g_kT[(h * HD + c * 4) * NK + kbase];
    float4 kq0 = *(const float4*)&kp[0 * NK];
    float4 kq1 = *(const float4*)&kp[1 * NK];
    float4 kq2 = *(const float4*)&kp[2 * NK];
    float4 kq3 = *(const float4*)&kp[3 * NK];
#pragma unroll
    for (int qi = 0; qi < 8; qi++) {
      float4 qv = *(const float4*)&S.sQ[qi][c * 4];
      acc[0][qi] = fmaf(qv.x, kq0.x, acc[0][qi]);
      acc[0][qi] = fmaf(qv.y, kq1.x, acc[0][qi]);
      acc[0][qi] = fmaf(qv.z, kq2.x, acc[0][qi]);
      acc[0][qi] = fmaf(qv.w, kq3.x, acc[0][qi]);
      acc[1][qi] = fmaf(qv.x, kq0.y, acc[1][qi]);
      acc[1][qi] = fmaf(qv.y, kq1.y, acc[1][qi]);
      acc[1][qi] = fmaf(qv.z, kq2.y, acc[1][qi]);
      acc[1][qi] = fmaf(qv.w, kq3.y, acc[1][qi]);
      acc[2][qi] = fmaf(qv.x, kq0.z, acc[2][qi]);
      acc[2][qi] = fmaf(qv.y, kq1.z, acc[2][qi]);
      acc[2][qi] = fmaf(qv.z, kq2.z, acc[2][qi]);
      acc[2][qi] = fmaf(qv.w, kq3.z, acc[2][qi]);
      acc[3][qi] = fmaf(qv.x, kq0.w, acc[3][qi]);
      acc[3][qi] = fmaf(qv.y, kq1.w, acc[3][qi]);
      acc[3][qi] = fmaf(qv.z, kq2.w, acc[3][qi]);
      acc[3][qi] = fmaf(qv.w, kq3.w, acc[3][qi]);
    }
  }

  // ---- CPB bias + padding (float2 interleaved table) ----
  {
    float4 p4 = *(const float4*)&pad[kbase];
    float pv[4] = {100.f * p4.x, 100.f * p4.y, 100.f * p4.z, 100.f * p4.w};
#pragma unroll
    for (int qi = 0; qi < 8; qi++) {
      float4 a4 = *(const float4*)&am[(q0 + qi) * NK + kbase];
      ushort4 x4 = *(const ushort4*)&g_sidx[(q0 + qi) * NK + kbase];
      float2 fg0 = S.sFG[x4.x];
      float2 fg1 = S.sFG[x4.y];
      float2 fg2 = S.sFG[x4.z];
      float2 fg3 = S.sFG[x4.w];
      acc[0][qi] += fmaf(a4.x, fg0.x, fg0.y) - pv[0];
      acc[1][qi] += fmaf(a4.y, fg1.x, fg1.y) - pv[1];
      acc[2][qi] += fmaf(a4.z, fg2.x, fg2.y) - pv[2];
      acc[3][qi] += fmaf(a4.w, fg3.x, fg3.y) - pv[3];
    }
  }

  // ---- block max per query ----
  float m[8];
#pragma unroll
  for (int qi = 0; qi < 8; qi++)
    m[qi] = fmaxf(fmaxf(acc[0][qi], acc[1][qi]), fmaxf(acc[2][qi], acc[3][qi]));
#pragma unroll
  for (int o = 16; o; o >>= 1)
#pragma unroll
    for (int qi = 0; qi < 8; qi++)
      m[qi] = fmaxf(m[qi], __shfl_xor_sync(FULLMASK, m[qi], o));
  if (lane == 0)
#pragma unroll
    for (int qi = 0; qi < 8; qi++) S.sRed[qi][w] = m[qi];
  __syncthreads();
#pragma unroll
  for (int qi = 0; qi < 8; qi++) {
    float4 r0 = *(const float4*)&S.sRed[qi][0];
    float4 r1 = *(const float4*)&S.sRed[qi][4];
    m[qi] = fmaxf(fmaxf(fmaxf(r0.x, r0.y), fmaxf(r0.z, r0.w)),
                  fmaxf(fmaxf(r1.x, r1.y), fmaxf(r1.z, r1.w)));
  }

  // ---- exp + sum ----
  float s[8];
#pragma unroll
  for (int qi = 0; qi < 8; qi++) {
    float e0 = __expf(acc[0][qi] - m[qi]);
    float e1 = __expf(acc[1][qi] - m[qi]);
    float e2 = __expf(acc[2][qi] - m[qi]);
    float e3 = __expf(acc[3][qi] - m[qi]);
    acc[0][qi] = e0;
    acc[1][qi] = e1;
    acc[2][qi] = e2;
    acc[3][qi] = e3;
    s[qi] = (e0 + e1) + (e2 + e3);
  }
#pragma unroll
  for (int o = 16; o; o >>= 1)
#pragma unroll
    for (int qi = 0; qi < 8; qi++)
      s[qi] += __shfl_xor_sync(FULLMASK, s[qi], o);
  __syncthreads();  // all sRed max reads done
  if (lane == 0)
#pragma unroll
    for (int qi = 0; qi < 8; qi++) S.sRed[qi][w] = s[qi];
  __syncthreads();
  float inv[8];
#pragma unroll
  for (int qi = 0; qi < 8; qi++) {
    float4 r0 = *(const float4*)&S.sRed[qi][0];
    float4 r1 = *(const float4*)&S.sRed[qi][4];
    inv[qi] = 1.f / ((r0.x + r0.y) + (r0.z + r0.w) + (r1.x + r1.y) + (r1.z + r1.w));
  }

  // ---- store NORMALIZED probs (all 8 queries, single pass) ----
#pragma unroll
  for (int kg = 0; kg < 4; kg++) {
    *(float4*)&S.u.sP[kbase + kg][0] =
        make_float4(acc[kg][0] * inv[0], acc[kg][1] * inv[1],
                    acc[kg][2] * inv[2], acc[kg][3] * inv[3]);
    *(float4*)&S.u.sP[kbase + kg][4] =
        make_float4(acc[kg][4] * inv[4], acc[kg][5] * inv[5],
                    acc[kg][6] * inv[6], acc[kg][7] * inv[7]);
  }
  __syncthreads();

  // ---- AV single pass: warp owns keys [w*128, w*128+128); f32x2 ----
  unsigned long long out2[4] = {0ull, 0ull, 0ull, 0ull};
  const float* vb = &g_v[(w * 128) * DIM + h * HD + lane];
#pragma unroll 8
  for (int jj = 0; jj < 128; jj++) {
    float vv = __ldg(&vb[jj * DIM]);
    unsigned long long vvp = pk2(vv, vv);
    ulonglong2 p01 = *(const ulonglong2*)&S.u.sP[w * 128 + jj][0];
    ulonglong2 p23 = *(const ulonglong2*)&S.u.sP[w * 128 + jj][4];
    fma2(out2[0], p01.x, vvp);
    fma2(out2[1], p01.y, vvp);
    fma2(out2[2], p23.x, vvp);
    fma2(out2[3], p23.y, vvp);
  }
  __syncthreads();  // all sP reads done before sOut alias write

  // ---- cross-warp x reduction into sQ (x-slice [8q][32d]) ----
  float out[8];
#pragma unroll
  for (int p = 0; p < 4; p++) upk2(out[2 * p], out[2 * p + 1], out2[p]);
#pragma unroll
  for (int qi = 0; qi < 8; qi++) S.u.sOut[w][qi][lane] = out[qi];
  __syncthreads();
  {
    float accf = 0.f;
#pragma unroll
    for (int ww = 0; ww < 8; ww++) accf += S.u.sOut[ww][w][lane];
    S.sQ[w][lane] = accf;  // x[q0+w][h*32+lane]
  }
  __syncthreads();

  // ---- fused output projection: (8x32 x-slice) @ Wp[h*32: , :] ----
  float acc8[8] = {};
  const float* wp = &Wp[(h * HD) * DIM + t];
#pragma unroll
  for (int d4 = 0; d4 < 8; d4++) {
    float wv0 = __ldg(&wp[(d4 * 4 + 0) * DIM]);
    float wv1 = __ldg(&wp[(d4 * 4 + 1) * DIM]);
    float wv2 = __ldg(&wp[(d4 * 4 + 2) * DIM]);
    float wv3 = __ldg(&wp[(d4 * 4 + 3) * DIM]);
#pragma unroll
    for (int qi = 0; qi < 8; qi++) {
      float4 xv = *(const float4*)&S.sQ[qi][d4 * 4];
      acc8[qi] = fmaf(xv.x, wv0, acc8[qi]);
      acc8[qi] = fmaf(xv.y, wv1, acc8[qi]);
      acc8[qi] = fmaf(xv.z, wv2, acc8[qi]);
      acc8[qi] = fmaf(xv.w, wv3, acc8[qi]);
    }
  }
#pragma unroll
  for (int qi = 0; qi < 8; qi++)
    atomicAdd(&outp[(q0 + qi) * DIM + t], acc8[qi]);
}

// ---------------- launch ------------------------------------------------
extern "C" void kernel_launch(void* const* d_in, const int* in_sizes, int n_in,
                              void* d_out, int out_size) {
  const float* query = (const float*)d_in[0];
  const float* kin   = (const float*)d_in[1];
  const float* vin   = (const float*)d_in[2];
  const float* pad   = (const float*)d_in[3];
  const float* am    = (const float*)d_in[4];
  const float* Wq    = (const float*)d_in[5];
  const float* bq    = (const float*)d_in[6];
  const float* Wk    = (const float*)d_in[7];
  const float* bk    = (const float*)d_in[8];
  const float* Wv    = (const float*)d_in[9];
  const float* bv    = (const float*)d_in[10];
  const float* Wp    = (const float*)d_in[11];
  const float* bp    = (const float*)d_in[12];
  const float* W1    = (const float*)d_in[13];
  const float* b1    = (const float*)d_in[14];
  const float* W2    = (const float*)d_in[15];
  float* out = (float*)d_out;

  cpb_sort<<<1, RPE>>>(W1, b1);
  mid<<<680, 256>>>(query, kin, vin, Wq, bq, Wk, bk, Wv, bv, am, bp,
                    W1, b1, W2, out);
  attention<<<dim3(NQ / 8, HEADS), 256>>>(pad, am, Wp, out);
}

// round 17
// speedup vs baseline: 1.2116x; 1.0915x over previous
#include <cuda_runtime.h>
#include <math.h>

#define NQ 512
#define NK 1024
#define DIM 256
#define HEADS 8
#define HD 32
#define RPE 512
#define SCALE 0.17677669529663687f
#define FULLMASK 0xffffffffu

// ---------------- packed fp32x2 helpers ----------------------------------
__device__ __forceinline__ unsigned long long pk2(float lo, float hi) {
  unsigned long long r;
  asm("mov.b64 %0, {%1, %2};" : "=l"(r) : "f"(lo), "f"(hi));
  return r;
}
__device__ __forceinline__ void upk2(float& lo, float& hi, unsigned long long v) {
  asm("mov.b64 {%0, %1}, %2;" : "=f"(lo), "=f"(hi) : "l"(v));
}
__device__ __forceinline__ void fma2(unsigned long long& d, unsigned long long a,
                                     unsigned long long b) {
  asm("fma.rn.f32x2 %0, %1, %2, %0;" : "+l"(d) : "l"(a), "l"(b));
}

// ---------------- scratch (device globals; no allocation) ----------------
__device__ float g_q[NQ * DIM];
__device__ float g_kT[DIM * NK];  // K TRANSPOSED: [d][key]
__device__ float g_v[NK * DIM];
__device__ float g_tsort[RPE];
__device__ int g_sord[RPE];
__device__ float g_F[HEADS * (RPE + 1)];
__device__ float g_G[HEADS * (RPE + 1)];
__device__ unsigned short g_sidx[NQ * NK];

// ---------------- cpb_sort: PARALLEL rank-count (32 blocks) --------------
// Block b handles elements [b*16, b*16+16). 8 threads per element, each
// covering 64 keys; ranks combined with 3 shfl_xor steps.
__global__ void __launch_bounds__(128) cpb_sort(const float* __restrict__ W1v,
                                                const float* __restrict__ b1v) {
  __shared__ float skey[RPE];
  int t = threadIdx.x;
  for (int i = t; i < RPE; i += 128) {
    float w1 = W1v[i], bb = b1v[i];
    skey[i] = (w1 != 0.f) ? (-bb / w1) : INFINITY;
  }
  __syncthreads();
  int e = blockIdx.x * 16 + (t >> 3);  // element this group ranks
  int sub = t & 7;                     // sub-slice 0..7
  float key = skey[e];
  int rank = 0;
  int jb = sub * 64;
#pragma unroll 4
  for (int j = 0; j < 64; j += 4) {
    float4 kj = *(const float4*)&skey[jb + j];
    int j0 = jb + j;
    rank += (kj.x < key || (kj.x == key && (j0 + 0) < e)) ? 1 : 0;
    rank += (kj.y < key || (kj.y == key && (j0 + 1) < e)) ? 1 : 0;
    rank += (kj.z < key || (kj.z == key && (j0 + 2) < e)) ? 1 : 0;
    rank += (kj.w < key || (kj.w == key && (j0 + 3) < e)) ? 1 : 0;
  }
#pragma unroll
  for (int o = 4; o; o >>= 1) rank += __shfl_xor_sync(FULLMASK, rank, o);
  if (sub == 0) {
    g_tsort[rank] = key;
    g_sord[rank] = e;
  }
}

// ---------------- mid: QKV GEMMs + cpb_index + CPB tables, one launch ----
// blocks 0..159   : two 128-thread GEMM tile groups (320 tiles)
// blocks 160..671 : cpb_index rows + d_out init (uses g_tsort)
// blocks 672..679 : F/G table build for head (blockIdx.x-672) (uses g_sord)
__global__ void __launch_bounds__(256) mid(
    const float* __restrict__ query, const float* __restrict__ kin,
    const float* __restrict__ vin,
    const float* __restrict__ Wq, const float* __restrict__ bq,
    const float* __restrict__ Wk, const float* __restrict__ bk,
    const float* __restrict__ Wv, const float* __restrict__ bv,
    const float* __restrict__ am, const float* __restrict__ bp,
    const float* __restrict__ W1v, const float* __restrict__ b1v,
    const float* __restrict__ W2v, float* __restrict__ outp) {
  int t = threadIdx.x;
  __shared__ float As[2][16][36];
  __shared__ float Bs[2][16][64];
  __shared__ float st[RPE];
  __shared__ float swt[8][4];
  __shared__ float sRed2[2][8];

  if (blockIdx.x < 160) {
    int g = t >> 7, lt = t & 127;
    int id = blockIdx.x * 2 + g;  // 0..319, all active
    int sel, tloc;
    if (id < 64) { sel = 0; tloc = id; }
    else if (id < 192) { sel = 1; tloc = id - 64; }
    else { sel = 2; tloc = id - 192; }
    const float* A = (sel == 0) ? query : (sel == 1) ? kin : vin;
    const float* W = (sel == 0) ? Wq : (sel == 1) ? Wk : Wv;
    const float* bias = (sel == 0) ? bq : (sel == 1) ? bk : bv;
    int bm = (tloc >> 2) * 32;
    int bn = (tloc & 3) * 64;

    int tx = lt % 16, ty = lt / 16;
    float acc[4][4] = {};

    for (int k0 = 0; k0 < 256; k0 += 16) {
      {
        int r = lt >> 2, c4 = lt & 3;
        float4 av = *(const float4*)&A[(bm + r) * 256 + k0 + c4 * 4];
        As[g][c4 * 4 + 0][r] = av.x;
        As[g][c4 * 4 + 1][r] = av.y;
        As[g][c4 * 4 + 2][r] = av.z;
        As[g][c4 * 4 + 3][r] = av.w;
      }
#pragma unroll
      for (int u = 0; u < 2; u++) {
        int idx = lt * 2 + u;
        int rr = idx >> 4, cc = idx & 15;
        *(float4*)&Bs[g][rr][cc * 4] =
            *(const float4*)&W[(k0 + rr) * 256 + bn + cc * 4];
      }
      __syncthreads();
#pragma unroll
      for (int k = 0; k < 16; k++) {
        float a[4], b[4];
#pragma unroll
        for (int i = 0; i < 4; i++) a[i] = As[g][k][ty * 4 + i];
#pragma unroll
        for (int j = 0; j < 4; j++) b[j] = Bs[g][k][tx * 4 + j];
#pragma unroll
        for (int i = 0; i < 4; i++)
#pragma unroll
          for (int j = 0; j < 4; j++) acc[i][j] = fmaf(a[i], b[j], acc[i][j]);
      }
      __syncthreads();
    }
    if (sel == 0) {
#pragma unroll
      for (int i = 0; i < 4; i++) {
        int row = bm + ty * 4 + i;
#pragma unroll
        for (int j = 0; j < 4; j++) {
          int col = bn + tx * 4 + j;
          g_q[row * 256 + col] = acc[i][j] + bias[col];
        }
      }
    } else if (sel == 2) {
#pragma unroll
      for (int i = 0; i < 4; i++) {
        int row = bm + ty * 4 + i;
#pragma unroll
        for (int j = 0; j < 4; j++) {
          int col = bn + tx * 4 + j;
          g_v[row * 256 + col] = acc[i][j] + bias[col];
        }
      }
    } else {  // K: transposed scatter store (proven path)
#pragma unroll
      for (int i = 0; i < 4; i++) {
        int row = bm + ty * 4 + i;
#pragma unroll
        for (int j = 0; j < 4; j++) {
          int col = bn + tx * 4 + j;
          g_kT[col * NK + row] = acc[i][j] + bias[col];
        }
      }
    }
    return;
  }

  if (blockIdx.x < 672) {
    // ---------------- cpb_index part ----------------
    int b = blockIdx.x - 160;  // 0..511
    for (int i = t; i < RPE; i += 256) st[i] = g_tsort[i];
    outp[b * 256 + t] = bp[t];  // init d_out with bias
    __syncthreads();
    int base = (b * 256 + t) * 4;
    float4 a4 = *(const float4*)&am[base];
    float av[4] = {a4.x, a4.y, a4.z, a4.w};
    unsigned short res[4];
#pragma unroll
    for (int u = 0; u < 4; u++) {
      int pos = 0;
#pragma unroll
      for (int sgm = 256; sgm >= 1; sgm >>= 1)
        if (st[pos + sgm - 1] < av[u]) pos += sgm;
      res[u] = (unsigned short)pos;
    }
    *(ushort4*)&g_sidx[base] = make_ushort4(res[0], res[1], res[2], res[3]);
    return;
  }

  // ---------------- CPB table build for one head ----------------
  {
    int h = blockIdx.x - 672;
    int lane = t & 31, warp = t >> 5;  // 8 warps

    int r0 = g_sord[t], r1 = g_sord[t + 256];

    float w1a = W1v[r0], b1a = b1v[r0], w2a = W2v[r0 * HEADS + h];
    bool negA = (w1a < 0.f), posA = (w1a > 0.f), zeroA = (!negA && !posA);
    float sgnA = posA ? 1.f : (negA ? -1.f : 0.f);
    float cwA = sgnA * w1a * w2a, cbA = sgnA * b1a * w2a;
    float f0A = negA ? (w1a * w2a) : 0.f;
    float g0A = negA ? (b1a * w2a) : ((zeroA && b1a > 0.f) ? (b1a * w2a) : 0.f);

    float w1b = W1v[r1], b1b = b1v[r1], w2b = W2v[r1 * HEADS + h];
    bool negB = (w1b < 0.f), posB = (w1b > 0.f), zeroB = (!negB && !posB);
    float sgnB = posB ? 1.f : (negB ? -1.f : 0.f);
    float cwB = sgnB * w1b * w2b, cbB = sgnB * b1b * w2b;
    float f0B = negB ? (w1b * w2b) : 0.f;
    float g0B = negB ? (b1b * w2b) : ((zeroB && b1b > 0.f) ? (b1b * w2b) : 0.f);

    float fr = f0A + f0B, gr = g0A + g0B;
#pragma unroll
    for (int o = 16; o; o >>= 1) {
      fr += __shfl_xor_sync(FULLMASK, fr, o);
      gr += __shfl_xor_sync(FULLMASK, gr, o);
    }
    if (lane == 0) {
      sRed2[0][warp] = fr;
      sRed2[1][warp] = gr;
    }
    __syncthreads();
    float F0 = 0.f, G0 = 0.f;
#pragma unroll
    for (int ww = 0; ww < 8; ww++) {
      F0 += sRed2[0][ww];
      G0 += sRed2[1][ww];
    }
    __syncthreads();

    float sc[4] = {cwA, cbA, cwB, cbB};
    float orig[4] = {cwA, cbA, cwB, cbB};
#pragma unroll
    for (int o = 1; o < 32; o <<= 1) {
#pragma unroll
      for (int q = 0; q < 4; q++) {
        float v = __shfl_up_sync(FULLMASK, sc[q], o);
        if (lane >= o) sc[q] += v;
      }
    }
    if (lane == 31)
#pragma unroll
      for (int q = 0; q < 4; q++) swt[warp][q] = sc[q];
    __syncthreads();
    float woff[4] = {0.f, 0.f, 0.f, 0.f};
    float tot[4] = {0.f, 0.f, 0.f, 0.f};
#pragma unroll
    for (int ww = 0; ww < 8; ww++)
#pragma unroll
      for (int q = 0; q < 4; q++) {
        float v = swt[ww][q];
        if (ww < warp) woff[q] += v;
        tot[q] += v;
      }
    float excl[4];
#pragma unroll
    for (int q = 0; q < 4; q++) excl[q] = sc[q] + woff[q] - orig[q];

    float* Fh = &g_F[h * (RPE + 1)];
    float* Gh = &g_G[h * (RPE + 1)];
    Fh[t] = F0 + excl[0];
    Gh[t] = G0 + excl[1];
    Fh[t + 256] = F0 + tot[0] + excl[2];
    Gh[t + 256] = G0 + tot[1] + excl[3];
    if (t == 0) {
      Fh[RPE] = F0 + tot[0] + tot[2];
      Gh[RPE] = G0 + tot[1] + tot[3];
    }
  }
}

// ---------------- fused attention + output projection --------------------
struct AttnSmem {
  float sQ[8][32];  // @0: scaled Q, later reused as x-slice for projection
  union {
    float sP[NK][8];       // 32KB: normalized probs (single pass)
    float sOut[8][8][32];  // 8KB epilogue
  } u;                     // @1024
  float sRed[8][8];        // @33792 (16B aligned)
  float2 sFG[RPE + 4];     // interleaved F/G tables
};  // ~37.3KB static

__global__ void __launch_bounds__(256, 4) attention(
    const float* __restrict__ pad, const float* __restrict__ am,
    const float* __restrict__ Wp, float* __restrict__ outp) {
  __shared__ AttnSmem S;
  const int h = blockIdx.y;
  const int q0 = blockIdx.x * 8;
  const int t = threadIdx.x;
  const int lane = t & 31, w = t >> 5;
  const int kbase = 4 * t;

  S.sQ[w][lane] = g_q[(q0 + w) * DIM + h * HD + lane] * SCALE;
  for (int i = t; i <= RPE; i += 256)
    S.sFG[i] = make_float2(g_F[h * (RPE + 1) + i], g_G[h * (RPE + 1) + i]);
  __syncthreads();

  // ---- QK: acc[kg][qi], K via transposed coalesced LDG ----
  float acc[4][8];
#pragma unroll
  for (int kg = 0; kg < 4; kg++)
#pragma unroll
    for (int qi = 0; qi < 8; qi++) acc[kg][qi] = 0.f;

#pragma unroll
  for (int c = 0; c < 8; c++) {
    const float* kp = &g_kT[(h * HD + c * 4) * NK + kbase];
    float4 kq0 = *(const float4*)&kp[0 * NK];
    float4 kq1 = *(const float4*)&kp[1 * NK];
    float4 kq2 = *(const float4*)&kp[2 * NK];
    float4 kq3 = *(const float4*)&kp[3 * NK];
#pragma unroll
    for (int qi = 0; qi < 8; qi++) {
      float4 qv = *(const float4*)&S.sQ[qi][c * 4];
      acc[0][qi] = fmaf(qv.x, kq0.x, acc[0][qi]);
      acc[0][qi] = fmaf(qv.y, kq1.x, acc[0][qi]);
      acc[0][qi] = fmaf(qv.z, kq2.x, acc[0][qi]);
      acc[0][qi] = fmaf(qv.w, kq3.x, acc[0][qi]);
      acc[1][qi] = fmaf(qv.x, kq0.y, acc[1][qi]);
      acc[1][qi] = fmaf(qv.y, kq1.y, acc[1][qi]);
      acc[1][qi] = fmaf(qv.z, kq2.y, acc[1][qi]);
      acc[1][qi] = fmaf(qv.w, kq3.y, acc[1][qi]);
      acc[2][qi] = fmaf(qv.x, kq0.z, acc[2][qi]);
      acc[2][qi] = fmaf(qv.y, kq1.z, acc[2][qi]);
      acc[2][qi] = fmaf(qv.z, kq2.z, acc[2][qi]);
      acc[2][qi] = fmaf(qv.w, kq3.z, acc[2][qi]);
      acc[3][qi] = fmaf(qv.x, kq0.w, acc[3][qi]);
      acc[3][qi] = fmaf(qv.y, kq1.w, acc[3][qi]);
      acc[3][qi] = fmaf(qv.z, kq2.w, acc[3][qi]);
      acc[3][qi] = fmaf(qv.w, kq3.w, acc[3][qi]);
    }
  }

  // ---- CPB bias + padding (float2 interleaved table) ----
  {
    float4 p4 = *(const float4*)&pad[kbase];
    float pv[4] = {100.f * p4.x, 100.f * p4.y, 100.f * p4.z, 100.f * p4.w};
#pragma unroll
    for (int qi = 0; qi < 8; qi++) {
      float4 a4 = *(const float4*)&am[(q0 + qi) * NK + kbase];
      ushort4 x4 = *(const ushort4*)&g_sidx[(q0 + qi) * NK + kbase];
      float2 fg0 = S.sFG[x4.x];
      float2 fg1 = S.sFG[x4.y];
      float2 fg2 = S.sFG[x4.z];
      float2 fg3 = S.sFG[x4.w];
      acc[0][qi] += fmaf(a4.x, fg0.x, fg0.y) - pv[0];
      acc[1][qi] += fmaf(a4.y, fg1.x, fg1.y) - pv[1];
      acc[2][qi] += fmaf(a4.z, fg2.x, fg2.y) - pv[2];
      acc[3][qi] += fmaf(a4.w, fg3.x, fg3.y) - pv[3];
    }
  }

  // ---- block max per query ----
  float m[8];
#pragma unroll
  for (int qi = 0; qi < 8; qi++)
    m[qi] = fmaxf(fmaxf(acc[0][qi], acc[1][qi]), fmaxf(acc[2][qi], acc[3][qi]));
#pragma unroll
  for (int o = 16; o; o >>= 1)
#pragma unroll
    for (int qi = 0; qi < 8; qi++)
      m[qi] = fmaxf(m[qi], __shfl_xor_sync(FULLMASK, m[qi], o));
  if (lane == 0)
#pragma unroll
    for (int qi = 0; qi < 8; qi++) S.sRed[qi][w] = m[qi];
  __syncthreads();
#pragma unroll
  for (int qi = 0; qi < 8; qi++) {
    float4 r0 = *(const float4*)&S.sRed[qi][0];
    float4 r1 = *(const float4*)&S.sRed[qi][4];
    m[qi] = fmaxf(fmaxf(fmaxf(r0.x, r0.y), fmaxf(r0.z, r0.w)),
                  fmaxf(fmaxf(r1.x, r1.y), fmaxf(r1.z, r1.w)));
  }

  // ---- exp + sum ----
  float s[8];
#pragma unroll
  for (int qi = 0; qi < 8; qi++) {
    float e0 = __expf(acc[0][qi] - m[qi]);
    float e1 = __expf(acc[1][qi] - m[qi]);
    float e2 = __expf(acc[2][qi] - m[qi]);
    float e3 = __expf(acc[3][qi] - m[qi]);
    acc[0][qi] = e0;
    acc[1][qi] = e1;
    acc[2][qi] = e2;
    acc[3][qi] = e3;
    s[qi] = (e0 + e1) + (e2 + e3);
  }
#pragma unroll
  for (int o = 16; o; o >>= 1)
#pragma unroll
    for (int qi = 0; qi < 8; qi++)
      s[qi] += __shfl_xor_sync(FULLMASK, s[qi], o);
  __syncthreads();  // all sRed max reads done
  if (lane == 0)
#pragma unroll
    for (int qi = 0; qi < 8; qi++) S.sRed[qi][w] = s[qi];
  __syncthreads();
  float inv[8];
#pragma unroll
  for (int qi = 0; qi < 8; qi++) {
    float4 r0 = *(const float4*)&S.sRed[qi][0];
    float4 r1 = *(const float4*)&S.sRed[qi][4];
    inv[qi] = 1.f / ((r0.x + r0.y) + (r0.z + r0.w) + (r1.x + r1.y) + (r1.z + r1.w));
  }

  // ---- store NORMALIZED probs (all 8 queries, single pass) ----
#pragma unroll
  for (int kg = 0; kg < 4; kg++) {
    *(float4*)&S.u.sP[kbase + kg][0] =
        make_float4(acc[kg][0] * inv[0], acc[kg][1] * inv[1],
                    acc[kg][2] * inv[2], acc[kg][3] * inv[3]);
    *(float4*)&S.u.sP[kbase + kg][4] =
        make_float4(acc[kg][4] * inv[4], acc[kg][5] * inv[5],
                    acc[kg][6] * inv[6], acc[kg][7] * inv[7]);
  }
  __syncthreads();

  // ---- AV single pass: warp owns keys [w*128, w*128+128); f32x2 ----
  unsigned long long out2[4] = {0ull, 0ull, 0ull, 0ull};
  const float* vb = &g_v[(w * 128) * DIM + h * HD + lane];
#pragma unroll 8
  for (int jj = 0; jj < 128; jj++) {
    float vv = __ldg(&vb[jj * DIM]);
    unsigned long long vvp = pk2(vv, vv);
    ulonglong2 p01 = *(const ulonglong2*)&S.u.sP[w * 128 + jj][0];
    ulonglong2 p23 = *(const ulonglong2*)&S.u.sP[w * 128 + jj][4];
    fma2(out2[0], p01.x, vvp);
    fma2(out2[1], p01.y, vvp);
    fma2(out2[2], p23.x, vvp);
    fma2(out2[3], p23.y, vvp);
  }
  __syncthreads();  // all sP reads done before sOut alias write

  // ---- cross-warp x reduction into sQ (x-slice [8q][32d]) ----
  float out[8];
#pragma unroll
  for (int p = 0; p < 4; p++) upk2(out[2 * p], out[2 * p + 1], out2[p]);
#pragma unroll
  for (int qi = 0; qi < 8; qi++) S.u.sOut[w][qi][lane] = out[qi];
  __syncthreads();
  {
    float accf = 0.f;
#pragma unroll
    for (int ww = 0; ww < 8; ww++) accf += S.u.sOut[ww][w][lane];
    S.sQ[w][lane] = accf;  // x[q0+w][h*32+lane]
  }
  __syncthreads();

  // ---- fused output projection: (8x32 x-slice) @ Wp[h*32: , :] ----
  float acc8[8] = {};
  const float* wp = &Wp[(h * HD) * DIM + t];
#pragma unroll
  for (int d4 = 0; d4 < 8; d4++) {
    float wv0 = __ldg(&wp[(d4 * 4 + 0) * DIM]);
    float wv1 = __ldg(&wp[(d4 * 4 + 1) * DIM]);
    float wv2 = __ldg(&wp[(d4 * 4 + 2) * DIM]);
    float wv3 = __ldg(&wp[(d4 * 4 + 3) * DIM]);
#pragma unroll
    for (int qi = 0; qi < 8; qi++) {
      float4 xv = *(const float4*)&S.sQ[qi][d4 * 4];
      acc8[qi] = fmaf(xv.x, wv0, acc8[qi]);
      acc8[qi] = fmaf(xv.y, wv1, acc8[qi]);
      acc8[qi] = fmaf(xv.z, wv2, acc8[qi]);
      acc8[qi] = fmaf(xv.w, wv3, acc8[qi]);
    }
  }
#pragma unroll
  for (int qi = 0; qi < 8; qi++)
    atomicAdd(&outp[(q0 + qi) * DIM + t], acc8[qi]);
}

// ---------------- launch ------------------------------------------------
extern "C" void kernel_launch(void* const* d_in, const int* in_sizes, int n_in,
                              void* d_out, int out_size) {
  const float* query = (const float*)d_in[0];
  const float* kin   = (const float*)d_in[1];
  const float* vin   = (const float*)d_in[2];
  const float* pad   = (const float*)d_in[3];
  const float* am    = (const float*)d_in[4];
  const float* Wq    = (const float*)d_in[5];
  const float* bq    = (const float*)d_in[6];
  const float* Wk    = (const float*)d_in[7];
  const float* bk    = (const float*)d_in[8];
  const float* Wv    = (const float*)d_in[9];
  const float* bv    = (const float*)d_in[10];
  const float* Wp    = (const float*)d_in[11];
  const float* bp    = (const float*)d_in[12];
  const float* W1    = (const float*)d_in[13];
  const float* b1    = (const float*)d_in[14];
  const float* W2    = (const float*)d_in[15];
  float* out = (float*)d_out;

  cpb_sort<<<32, 128>>>(W1, b1);
  mid<<<680, 256>>>(query, kin, vin, Wq, bq, Wk, bk, Wv, bv, am, bp,
                    W1, b1, W2, out);
  attention<<<dim3(NQ / 8, HEADS), 256>>>(pad, am, Wp, out);
}